// round 2
// baseline (speedup 1.0000x reference)
#include <cuda_runtime.h>
#include <math.h>

// HawkesPointProcess: B=8, N=4096.
// out[b] = loglik[b] - compensator[b]
//   A_i = sum_{j<i} exp(-beta*(t_i - t_j))  (linear scan: A_i = e_i*(A_{i-1}+1))
//   lamb_i = A_i*alpha*beta + mu
//   loglik = sum_i log(lamb_i + 1e-8) * m_i
//   comp   = (t1-t0)*mu - alpha*( sum_i exp(-beta*(t1-t_i)*m_i + (1-m_i)*(-1e20)) - sum_i m_i )

#define NTHREADS 256
#define CHUNK 16   // NTHREADS*CHUNK == N == 4096

__device__ __forceinline__ float softplusf(float x) {
    // stable softplus; inputs here are ~N(0, 0.1) so the branch rarely matters
    return x > 20.0f ? x : log1pf(expf(x));
}

__global__ __launch_bounds__(NTHREADS, 1)
void hawkes_kernel(const float* __restrict__ et,
                   const float* __restrict__ mask,
                   const float* __restrict__ t0v,
                   const float* __restrict__ t1v,
                   const float* __restrict__ mu_raw,
                   const float* __restrict__ alpha_raw,
                   const float* __restrict__ beta_raw,
                   float* __restrict__ out,
                   int N) {
    const int b   = blockIdx.x;
    const int tid = threadIdx.x;

    const float mu    = softplusf(mu_raw[0]);
    const float alpha = softplusf(alpha_raw[0]);
    const float beta  = softplusf(beta_raw[0]);
    const float T0 = t0v[b];
    const float T1 = t1v[b];

    const float* t = et   + (size_t)b * N;
    const float* m = mask + (size_t)b * N;

    __shared__ float sG[NTHREADS];
    __shared__ float sH[NTHREADS];
    __shared__ float red[NTHREADS];

    const int base = tid * CHUNK;

    // Load this thread's chunk into registers.
    float tv[CHUNK], mv[CHUNK];
#pragma unroll
    for (int k = 0; k < CHUNK; k++) {
        tv[k] = t[base + k];
        mv[k] = m[base + k];
    }
    const float tprev = (base == 0) ? tv[0] : t[base - 1];

    // Phase 1: chunk-local affine composition (A_out = G*A_in + H).
    // Recurrence per element: A_k = exp(-beta*(t_k - t_{k-1})) * (A_{k-1} + 1);
    // global element 0 is defined as A_0 = 0.
    {
        float A = 0.0f;
        float p = tprev;
#pragma unroll
        for (int k = 0; k < CHUNK; k++) {
            if (base == 0 && k == 0) {
                A = 0.0f;
            } else {
                A = __expf(-beta * (tv[k] - p)) * (A + 1.0f);
            }
            p = tv[k];
        }
        sG[tid] = __expf(-beta * (tv[CHUNK - 1] - tprev));  // product of e_k over chunk
        sH[tid] = A;                                        // value with A_in = 0
    }
    __syncthreads();

    // Hillis-Steele inclusive scan over (G, H) with composition:
    // (cur ∘ prev): G = G_cur*G_prev, H = G_cur*H_prev + H_cur
    for (int off = 1; off < NTHREADS; off <<= 1) {
        float gp = 0.0f, hp = 0.0f;
        const bool act = (tid >= off);
        if (act) { gp = sG[tid - off]; hp = sH[tid - off]; }
        __syncthreads();
        if (act) {
            sH[tid] = sG[tid] * hp + sH[tid];
            sG[tid] = sG[tid] * gp;
        }
        __syncthreads();
    }
    const float A_in = (tid == 0) ? 0.0f : sH[tid - 1];
    __syncthreads();

    // Phase 2: replay chunk with the true incoming state; accumulate partials.
    float acc_log = 0.0f, acc_comp = 0.0f, acc_m = 0.0f;
    {
        float A = A_in;
        float p = tprev;
        const float ab = alpha * beta;
#pragma unroll
        for (int k = 0; k < CHUNK; k++) {
            if (base == 0 && k == 0) {
                A = 0.0f;
            } else {
                A = __expf(-beta * (tv[k] - p)) * (A + 1.0f);
            }
            p = tv[k];
            const float lamb = A * ab + mu;
            acc_log += logf(lamb + 1e-8f) * mv[k];
            // compensator kernel term (exact reference formula, handles mask generally)
            const float lk = -beta * (T1 - tv[k]) * mv[k] + (1.0f - mv[k]) * (-1e20f);
            acc_comp += __expf(lk);
            acc_m += mv[k];
        }
    }

    // Block reductions (3 scalars).
    red[tid] = acc_log;
    __syncthreads();
    for (int s = NTHREADS / 2; s > 0; s >>= 1) {
        if (tid < s) red[tid] += red[tid + s];
        __syncthreads();
    }
    const float tot_log = red[0];
    __syncthreads();

    red[tid] = acc_comp;
    __syncthreads();
    for (int s = NTHREADS / 2; s > 0; s >>= 1) {
        if (tid < s) red[tid] += red[tid + s];
        __syncthreads();
    }
    const float tot_comp = red[0];
    __syncthreads();

    red[tid] = acc_m;
    __syncthreads();
    for (int s = NTHREADS / 2; s > 0; s >>= 1) {
        if (tid < s) red[tid] += red[tid + s];
        __syncthreads();
    }
    const float tot_m = red[0];

    if (tid == 0) {
        float compensator = (T1 - T0) * mu - alpha * (tot_comp - tot_m);
        out[b] = tot_log - compensator;
    }
}

extern "C" void kernel_launch(void* const* d_in, const int* in_sizes, int n_in,
                              void* d_out, int out_size) {
    const float* event_times = (const float*)d_in[0];
    const float* input_mask  = (const float*)d_in[1];
    const float* t0          = (const float*)d_in[2];
    const float* t1          = (const float*)d_in[3];
    const float* mu          = (const float*)d_in[4];
    const float* alpha       = (const float*)d_in[5];
    const float* beta        = (const float*)d_in[6];
    float* out = (float*)d_out;

    const int B = in_sizes[2];              // t0 has B elements
    const int N = in_sizes[0] / B;          // event_times is B*N

    hawkes_kernel<<<B, NTHREADS>>>(event_times, input_mask, t0, t1,
                                   mu, alpha, beta, out, N);
}

// round 3
// speedup vs baseline: 1.1057x; 1.1057x over previous
#include <cuda_runtime.h>
#include <math.h>

// HawkesPointProcess: B=8, N=4096.
// out[b] = loglik[b] - compensator[b]
//   A_i = sum_{j<i} exp(-beta*(t_i - t_j)), sorted times => A_i = e_i*(A_{i-1}+1),
//   e_i = exp(-beta*(t_i - t_{i-1})), with e_0 := 0 so A_0 = 0.
//   lamb_i = A_i*alpha*beta + mu
//   loglik = sum_i log(lamb_i + 1e-8)*m_i
//   comp   = (t1-t0)*mu - alpha*( sum_i exp(-beta*(t1-t_i)*m_i + (1-m_i)*(-1e20)) - sum_i m_i )

#define NT 1024
#define CHUNK 4      // NT*CHUNK == N == 4096

__device__ __forceinline__ float softplusf(float x) {
    return x > 20.0f ? x : log1pf(expf(x));
}

__global__ __launch_bounds__(NT, 1)
void hawkes_kernel(const float* __restrict__ et,
                   const float* __restrict__ mask,
                   const float* __restrict__ t0v,
                   const float* __restrict__ t1v,
                   const float* __restrict__ mu_raw,
                   const float* __restrict__ alpha_raw,
                   const float* __restrict__ beta_raw,
                   float* __restrict__ out,
                   int N) {
    const int b    = blockIdx.x;
    const int tid  = threadIdx.x;
    const int lane = tid & 31;
    const int warp = tid >> 5;

    const float mu    = softplusf(mu_raw[0]);
    const float alpha = softplusf(alpha_raw[0]);
    const float beta  = softplusf(beta_raw[0]);
    const float T0 = t0v[b];
    const float T1 = t1v[b];

    const float* t = et   + (size_t)b * N;
    const float* m = mask + (size_t)b * N;

    __shared__ float sG[32];
    __shared__ float sH[32];
    __shared__ float r0[32], r1[32], r2[32];

    const int base = tid * CHUNK;

    // Coalesced vector loads.
    const float4 t4 = *reinterpret_cast<const float4*>(t + base);
    const float4 m4 = *reinterpret_cast<const float4*>(m + base);
    const float tprev = (tid == 0) ? t4.x : t[base - 1];

    // Per-element decay factors e_k (independent — all 4 MUFU exps overlap).
    float e0 = __expf(-beta * (t4.x - tprev));
    float e1 = __expf(-beta * (t4.y - t4.x));
    float e2 = __expf(-beta * (t4.z - t4.y));
    float e3 = __expf(-beta * (t4.w - t4.z));
    if (tid == 0) e0 = 0.0f;   // global element 0: A_0 = 0

    // Chunk-local affine transform (A_out = G*A_in + H), H = value at A_in=0.
    float H;
    {
        float A = e0;                 // e0*0 + e0
        A = fmaf(e1, A, e1);
        A = fmaf(e2, A, e2);
        A = fmaf(e3, A, e3);
        H = A;
    }
    float G = (e0 * e1) * (e2 * e3);

    // Inclusive warp scan over (G,H): compose(cur, prev) = (Gc*Gp, Gc*Hp + Hc).
    #pragma unroll
    for (int off = 1; off < 32; off <<= 1) {
        float Gp = __shfl_up_sync(0xffffffffu, G, off);
        float Hp = __shfl_up_sync(0xffffffffu, H, off);
        if (lane >= off) { H = fmaf(G, Hp, H); G *= Gp; }
    }
    // Lane-exclusive transform within warp.
    float Gex = __shfl_up_sync(0xffffffffu, G, 1);
    float Hex = __shfl_up_sync(0xffffffffu, H, 1);
    if (lane == 0) { Gex = 1.0f; Hex = 0.0f; }

    // Warp aggregates -> smem, warp 0 scans them.
    if (lane == 31) { sG[warp] = G; sH[warp] = H; }
    __syncthreads();
    if (warp == 0) {
        float g = sG[lane], h = sH[lane];
        #pragma unroll
        for (int off = 1; off < 32; off <<= 1) {
            float gp = __shfl_up_sync(0xffffffffu, g, off);
            float hp = __shfl_up_sync(0xffffffffu, h, off);
            if (lane >= off) { h = fmaf(g, hp, h); g *= gp; }
        }
        sH[lane] = h;   // inclusive warp-prefix values (applied to A=0)
    }
    __syncthreads();

    // Incoming state for this thread's chunk.
    const float Aw   = (warp == 0) ? 0.0f : sH[warp - 1];
    const float A_in = fmaf(Gex, Aw, Hex);

    // Phase 2: replay with true incoming state (e_k cached in registers).
    const float ab = alpha * beta;
    float acc_log, acc_comp, acc_m;
    {
        float A = A_in;
        A = fmaf(e0, A, e0);
        float l0 = __logf(fmaf(A, ab, mu) + 1e-8f);
        A = fmaf(e1, A, e1);
        float l1 = __logf(fmaf(A, ab, mu) + 1e-8f);
        A = fmaf(e2, A, e2);
        float l2 = __logf(fmaf(A, ab, mu) + 1e-8f);
        A = fmaf(e3, A, e3);
        float l3 = __logf(fmaf(A, ab, mu) + 1e-8f);
        acc_log = l0 * m4.x + l1 * m4.y + l2 * m4.z + l3 * m4.w;

        // Compensator kernel terms (exact reference formula incl. mask).
        float k0 = __expf(-beta * (T1 - t4.x) * m4.x + (1.0f - m4.x) * (-1e20f));
        float k1 = __expf(-beta * (T1 - t4.y) * m4.y + (1.0f - m4.y) * (-1e20f));
        float k2 = __expf(-beta * (T1 - t4.z) * m4.z + (1.0f - m4.z) * (-1e20f));
        float k3 = __expf(-beta * (T1 - t4.w) * m4.w + (1.0f - m4.w) * (-1e20f));
        acc_comp = (k0 + k1) + (k2 + k3);
        acc_m    = (m4.x + m4.y) + (m4.z + m4.w);
    }

    // Warp reductions (3 scalars, shuffle only).
    #pragma unroll
    for (int off = 16; off > 0; off >>= 1) {
        acc_log  += __shfl_xor_sync(0xffffffffu, acc_log,  off);
        acc_comp += __shfl_xor_sync(0xffffffffu, acc_comp, off);
        acc_m    += __shfl_xor_sync(0xffffffffu, acc_m,    off);
    }
    if (lane == 0) { r0[warp] = acc_log; r1[warp] = acc_comp; r2[warp] = acc_m; }
    __syncthreads();

    if (warp == 0) {
        float v0 = r0[lane], v1 = r1[lane], v2 = r2[lane];
        #pragma unroll
        for (int off = 16; off > 0; off >>= 1) {
            v0 += __shfl_xor_sync(0xffffffffu, v0, off);
            v1 += __shfl_xor_sync(0xffffffffu, v1, off);
            v2 += __shfl_xor_sync(0xffffffffu, v2, off);
        }
        if (lane == 0) {
            float compensator = (T1 - T0) * mu - alpha * (v1 - v2);
            out[b] = v0 - compensator;
        }
    }
}

extern "C" void kernel_launch(void* const* d_in, const int* in_sizes, int n_in,
                              void* d_out, int out_size) {
    const float* event_times = (const float*)d_in[0];
    const float* input_mask  = (const float*)d_in[1];
    const float* t0          = (const float*)d_in[2];
    const float* t1          = (const float*)d_in[3];
    const float* mu          = (const float*)d_in[4];
    const float* alpha       = (const float*)d_in[5];
    const float* beta        = (const float*)d_in[6];
    float* out = (float*)d_out;

    const int B = in_sizes[2];      // t0 has B elements
    const int N = in_sizes[0] / B;  // 4096

    hawkes_kernel<<<B, NT>>>(event_times, input_mask, t0, t1,
                             mu, alpha, beta, out, N);
}